// round 11
// baseline (speedup 1.0000x reference)
#include <cuda_runtime.h>
#include <cuda_bf16.h>
#include <math.h>
#include <stdint.h>

#define NF    32
#define NB    2048
#define NK    64
#define NH    64
#define PAIRS 496
#define VSTRU 44     // uints per bf16x2 row: 16B-aligned, rows spread over all 8 16B-classes
#define ZROW  32

// W fragment table, k-contiguous permutation: thread tig owns logical k [16tig,16tig+16)
__device__ uint2 g_wfrag[4 * 8 * 32];

__device__ __forceinline__ uint32_t pack_bf16x2(float lo, float hi) {
    __nv_bfloat162 h = __floats2bfloat162_rn(lo, hi);
    return *reinterpret_cast<uint32_t*>(&h);
}
__device__ __forceinline__ float2 unpack_bf16x2(uint32_t u) {
    __nv_bfloat162 h = *reinterpret_cast<__nv_bfloat162*>(&u);
    return __bfloat1622float2(h);
}
__device__ __forceinline__ uint32_t mul_bf16x2(uint32_t a, uint32_t b) {
    __nv_bfloat162 ha = *reinterpret_cast<__nv_bfloat162*>(&a);
    __nv_bfloat162 hb = *reinterpret_cast<__nv_bfloat162*>(&b);
    __nv_bfloat162 hc = __hmul2(ha, hb);
    return *reinterpret_cast<uint32_t*>(&hc);
}
__device__ __forceinline__ void mma_bf16(float& d0, float& d1, float& d2, float& d3,
                                         uint32_t a0, uint32_t a1, uint32_t a2, uint32_t a3,
                                         uint32_t b0, uint32_t b1) {
    asm volatile(
        "mma.sync.aligned.m16n8k16.row.col.f32.bf16.bf16.f32 "
        "{%0,%1,%2,%3}, {%4,%5,%6,%7}, {%8,%9}, {%0,%1,%2,%3};"
        : "+f"(d0), "+f"(d1), "+f"(d2), "+f"(d3)
        : "r"(a0), "r"(a1), "r"(a2), "r"(a3), "r"(b0), "r"(b1));
}
__device__ __forceinline__ void cp_async16(uint32_t smem_dst, const void* gsrc) {
    asm volatile("cp.async.ca.shared.global [%0], [%1], 16;"
                 :: "r"(smem_dst), "l"(gsrc) : "memory");
}

// ---- pre-kernel: pack W with k-contiguous permutation ----
__global__ void wfrag_build(const float* __restrict__ at_w) {
    int idx  = blockIdx.x * 256 + threadIdx.x;
    int lane = idx & 31;
    int tile = idx >> 5;
    int ks = tile >> 3, nt = tile & 7;
    int tig = lane & 3, gid = lane >> 2;
    int lk = 16 * tig + 4 * ks;
    int h  = nt * 8 + gid;
    uint2 v;
    v.x = pack_bf16x2(at_w[lk * NH + h],       at_w[(lk + 1) * NH + h]);
    v.y = pack_bf16x2(at_w[(lk + 2) * NH + h], at_w[(lk + 3) * NH + h]);
    g_wfrag[idx] = v;
}

__global__ __launch_bounds__(256, 2)
void afm_persist_kernel(const int*   __restrict__ x,      // [F, B]
                        const float* __restrict__ emb_v,  // [VOCAB, K]
                        const float* __restrict__ at_b,
                        const float* __restrict__ at_h,
                        const float* __restrict__ pvec,
                        const float* __restrict__ w0,
                        const float* __restrict__ w1,
                        float*       __restrict__ out)
{
    __shared__ uint32_t sVbf[(NF + 1) * VSTRU];   // bf16x2 operand (+ zero row)
    __shared__ float    stag[2][NF * NK];         // fp32 staging (cp.async), 16 KB
    __shared__ float4   sBA4[32];
    __shared__ unsigned char sI[512], sJ[512];
    __shared__ float    sPool[8][NK];
    __shared__ float    sPv[NK];
    __shared__ float    sFm1, sRed[2];

    const int tid  = threadIdx.x;
    const int w    = tid >> 5;
    const int lane = tid & 31;
    const int gid  = lane >> 2;
    const int tig  = lane & 3;
    const int pf_f = tid >> 3;          // prefetch: row
    const int pf_q = tid & 7;           // prefetch: 8-float chunk

    // ======== one-time prologue ========
    uint2 Wb[4][8];
    #pragma unroll
    for (int ks = 0; ks < 4; ks++)
        #pragma unroll
        for (int nt = 0; nt < 8; nt++)
            Wb[ks][nt] = __ldg(&g_wfrag[(ks * 8 + nt) * 32 + lane]);

    for (int p = tid; p < 512; p += 256) {
        if (p < PAIRS) {
            int pp = p, i = 0, off = 0;
            while (pp >= off + (NF - 1 - i)) { off += NF - 1 - i; i++; }
            sI[p] = (unsigned char)i;
            sJ[p] = (unsigned char)(i + 1 + pp - off);
        } else {
            sI[p] = ZROW; sJ[p] = ZROW;
        }
    }
    if (tid < VSTRU) sVbf[ZROW * VSTRU + tid] = 0u;
    if (tid < 32) {
        int nt = tid >> 2, tg = tid & 3;
        int h0 = nt * 8 + 2 * tg;
        sBA4[tid] = make_float4(__ldg(&at_b[h0]),     __ldg(&at_h[h0]),
                                __ldg(&at_b[h0 + 1]), __ldg(&at_h[h0 + 1]));
    }
    if (tid < NK) sPv[tid] = __ldg(&pvec[tid]);
    const float w0v = __ldg(w0);

    const uint32_t stag_b0 = (uint32_t)__cvta_generic_to_shared(&stag[0][0]);
    const uint32_t stag_b1 = (uint32_t)__cvta_generic_to_shared(&stag[1][0]);

    // ---- prefetch first unit ----
    int u = blockIdx.x;
    {
        int row = __ldg(&x[pf_f * NB + u]);
        const float* src = emb_v + row * NK + pf_q * 8;
        uint32_t dst = stag_b0 + (uint32_t)(pf_f * NK + pf_q * 8) * 4u;
        cp_async16(dst, src);
        cp_async16(dst + 16, src + 4);
        asm volatile("cp.async.commit_group;" ::: "memory");
    }

    int cur = 0;
    #pragma unroll 1
    for (; u < NB; u += gridDim.x, cur ^= 1) {
        const int unext = u + gridDim.x;

        asm volatile("cp.async.wait_group 0;" ::: "memory");
        __syncthreads();   // staging landed; previous iter's smem reads all done

        // ---- first-order FM for this unit (warp 0; consumed at the end) ----
        if (w == 0) {
            int row = __ldg(&x[lane * NB + u]);
            float v = __ldg(&w1[row]);
            #pragma unroll
            for (int off = 16; off >= 1; off >>= 1)
                v += __shfl_xor_sync(0xffffffffu, v, off);
            if (lane == 0) sFm1 = v + w0v;
        }

        // ---- convert staging -> bf16 operand (same-thread chunks, no race) ----
        {
            const float4* s4 = (const float4*)&stag[cur][pf_f * NK + pf_q * 8];
            float4 v0 = s4[0], v1 = s4[1];
            uint4 pk;
            pk.x = pack_bf16x2(v0.x, v0.y);
            pk.y = pack_bf16x2(v0.z, v0.w);
            pk.z = pack_bf16x2(v1.x, v1.y);
            pk.w = pack_bf16x2(v1.z, v1.w);
            *(uint4*)&sVbf[pf_f * VSTRU + 4 * pf_q] = pk;
        }

        // ---- prefetch next unit into the other staging buffer ----
        if (unext < NB) {
            int row = __ldg(&x[pf_f * NB + unext]);
            const float* src = emb_v + row * NK + pf_q * 8;
            uint32_t dst = (cur ? stag_b0 : stag_b1) +
                           (uint32_t)(pf_f * NK + pf_q * 8) * 4u;
            cp_async16(dst, src);
            cp_async16(dst + 16, src + 4);
            asm volatile("cp.async.commit_group;" ::: "memory");
        }
        __syncthreads();   // sVbf ready

        // ======== hot loop: 4 tiles of 128 pairs ========
        float pooled[16];
        #pragma unroll
        for (int s = 0; s < 16; s++) pooled[s] = 0.f;

        const int ub = 8 * tig;

        #pragma unroll 2
        for (int t = 0; t < 4; t++) {
            const int p1 = t * 128 + w * 16 + gid;
            const uint32_t* ri1 = sVbf + sI[p1] * VSTRU + ub;
            const uint32_t* rj1 = sVbf + sJ[p1] * VSTRU + ub;
            const uint32_t* ri2 = sVbf + sI[p1 + 8] * VSTRU + ub;
            const uint32_t* rj2 = sVbf + sJ[p1 + 8] * VSTRU + ub;

            uint4 i0 = *(const uint4*)ri1, i1 = *(const uint4*)(ri1 + 4);
            uint4 j0 = *(const uint4*)rj1, j1 = *(const uint4*)(rj1 + 4);
            uint4 m0 = *(const uint4*)ri2, m1 = *(const uint4*)(ri2 + 4);
            uint4 n0 = *(const uint4*)rj2, n1 = *(const uint4*)(rj2 + 4);

            uint32_t af[4][4];
            af[0][0] = mul_bf16x2(i0.x, j0.x);  af[0][2] = mul_bf16x2(i0.y, j0.y);
            af[1][0] = mul_bf16x2(i0.z, j0.z);  af[1][2] = mul_bf16x2(i0.w, j0.w);
            af[2][0] = mul_bf16x2(i1.x, j1.x);  af[2][2] = mul_bf16x2(i1.y, j1.y);
            af[3][0] = mul_bf16x2(i1.z, j1.z);  af[3][2] = mul_bf16x2(i1.w, j1.w);
            af[0][1] = mul_bf16x2(m0.x, n0.x);  af[0][3] = mul_bf16x2(m0.y, n0.y);
            af[1][1] = mul_bf16x2(m0.z, n0.z);  af[1][3] = mul_bf16x2(m0.w, n0.w);
            af[2][1] = mul_bf16x2(m1.x, n1.x);  af[2][3] = mul_bf16x2(m1.y, n1.y);
            af[3][1] = mul_bf16x2(m1.z, n1.z);  af[3][3] = mul_bf16x2(m1.w, n1.w);

            float s1 = 0.f, s2 = 0.f;
            #pragma unroll
            for (int nt = 0; nt < 8; nt++) {
                float d0 = 0.f, d1 = 0.f, d2 = 0.f, d3 = 0.f;
                #pragma unroll
                for (int ks = 0; ks < 4; ks++)
                    mma_bf16(d0, d1, d2, d3,
                             af[ks][0], af[ks][1], af[ks][2], af[ks][3],
                             Wb[ks][nt].x, Wb[ks][nt].y);
                float4 ba = sBA4[nt * 4 + tig];
                s1 += fmaxf(d0 + ba.x, 0.f) * ba.y + fmaxf(d1 + ba.z, 0.f) * ba.w;
                s2 += fmaxf(d2 + ba.x, 0.f) * ba.y + fmaxf(d3 + ba.z, 0.f) * ba.w;
            }
            s1 += __shfl_xor_sync(0xffffffffu, s1, 1);
            s1 += __shfl_xor_sync(0xffffffffu, s1, 2);
            s2 += __shfl_xor_sync(0xffffffffu, s2, 1);
            s2 += __shfl_xor_sync(0xffffffffu, s2, 2);

            #pragma unroll
            for (int ks = 0; ks < 4; ks++) {
                float2 v;
                v = unpack_bf16x2(af[ks][0]);
                pooled[ks * 4 + 0] = fmaf(s1, v.x, pooled[ks * 4 + 0]);
                pooled[ks * 4 + 1] = fmaf(s1, v.y, pooled[ks * 4 + 1]);
                v = unpack_bf16x2(af[ks][2]);
                pooled[ks * 4 + 2] = fmaf(s1, v.x, pooled[ks * 4 + 2]);
                pooled[ks * 4 + 3] = fmaf(s1, v.y, pooled[ks * 4 + 3]);
                v = unpack_bf16x2(af[ks][1]);
                pooled[ks * 4 + 0] = fmaf(s2, v.x, pooled[ks * 4 + 0]);
                pooled[ks * 4 + 1] = fmaf(s2, v.y, pooled[ks * 4 + 1]);
                v = unpack_bf16x2(af[ks][3]);
                pooled[ks * 4 + 2] = fmaf(s2, v.x, pooled[ks * 4 + 2]);
                pooled[ks * 4 + 3] = fmaf(s2, v.y, pooled[ks * 4 + 3]);
            }
        }

        // ---- reduce pooled across gid lanes ----
        #pragma unroll
        for (int s = 0; s < 16; s++) {
            pooled[s] += __shfl_xor_sync(0xffffffffu, pooled[s], 4);
            pooled[s] += __shfl_xor_sync(0xffffffffu, pooled[s], 8);
            pooled[s] += __shfl_xor_sync(0xffffffffu, pooled[s], 16);
        }
        if (gid == 0) {
            #pragma unroll
            for (int ks = 0; ks < 4; ks++)
                *(float4*)&sPool[w][16 * tig + 4 * ks] =
                    make_float4(pooled[ks * 4 + 0], pooled[ks * 4 + 1],
                                pooled[ks * 4 + 2], pooled[ks * 4 + 3]);
        }
        __syncthreads();

        if (tid < NK) {
            float v = 0.f;
            #pragma unroll
            for (int g = 0; g < 8; g++) v += sPool[g][tid];
            v *= sPv[tid];
            #pragma unroll
            for (int off = 16; off >= 1; off >>= 1)
                v += __shfl_xor_sync(0xffffffffu, v, off);
            if ((tid & 31) == 0) sRed[tid >> 5] = v;
        }
        __syncthreads();

        if (tid == 0) {
            float logit = sRed[0] + sRed[1] + sFm1;
            out[u] = 1.f / (1.f + expf(-logit));
        }
    }
}

extern "C" void kernel_launch(void* const* d_in, const int* in_sizes, int n_in,
                              void* d_out, int out_size) {
    const int*   x     = (const int*)  d_in[0];
    const float* emb_v = (const float*)d_in[1];
    const float* at_w  = (const float*)d_in[2];
    const float* at_b  = (const float*)d_in[3];
    const float* at_h  = (const float*)d_in[4];
    const float* pvec  = (const float*)d_in[5];
    const float* w0    = (const float*)d_in[6];
    const float* w1    = (const float*)d_in[7];
    float* out = (float*)d_out;

    static int grid = 0;
    if (!grid) {
        int dev = 0, sms = 148;
        cudaGetDevice(&dev);
        cudaDeviceGetAttribute(&sms, cudaDevAttrMultiProcessorCount, dev);
        grid = 2 * sms;
        if (grid > NB) grid = NB;
    }
    wfrag_build<<<4, 256>>>(at_w);
    afm_persist_kernel<<<grid, 256>>>(x, emb_v, at_b, at_h, pvec, w0, w1, out);
}

// round 14
// speedup vs baseline: 1.5131x; 1.5131x over previous
#include <cuda_runtime.h>
#include <cuda_bf16.h>
#include <math.h>
#include <stdint.h>

#define NF    32
#define NB    2048
#define NK    64
#define NH    64
#define PAIRS 496
#define VSTRU 44     // uints per bf16x2 row: 16B-aligned, rows spread over all 8 16B-classes
#define ZROW  32

// W fragment table, k-contiguous permutation: thread tig owns logical k [16tig,16tig+16)
__device__ uint2 g_wfrag[4 * 8 * 32];
// pvec fragment table: col 0 = pvec, cols 1..7 = 0   [ks(4)][lane(32)]
__device__ uint2 g_pfrag[4 * 32];

__device__ __forceinline__ uint32_t pack_bf16x2(float lo, float hi) {
    __nv_bfloat162 h = __floats2bfloat162_rn(lo, hi);
    return *reinterpret_cast<uint32_t*>(&h);
}
__device__ __forceinline__ uint32_t mul_bf16x2(uint32_t a, uint32_t b) {
    __nv_bfloat162 ha = *reinterpret_cast<__nv_bfloat162*>(&a);
    __nv_bfloat162 hb = *reinterpret_cast<__nv_bfloat162*>(&b);
    __nv_bfloat162 hc = __hmul2(ha, hb);
    return *reinterpret_cast<uint32_t*>(&hc);
}
__device__ __forceinline__ void mma_bf16(float& d0, float& d1, float& d2, float& d3,
                                         uint32_t a0, uint32_t a1, uint32_t a2, uint32_t a3,
                                         uint32_t b0, uint32_t b1) {
    asm volatile(
        "mma.sync.aligned.m16n8k16.row.col.f32.bf16.bf16.f32 "
        "{%0,%1,%2,%3}, {%4,%5,%6,%7}, {%8,%9}, {%0,%1,%2,%3};"
        : "+f"(d0), "+f"(d1), "+f"(d2), "+f"(d3)
        : "r"(a0), "r"(a1), "r"(a2), "r"(a3), "r"(b0), "r"(b1));
}

// ---- pre-kernel: pack W (k-contiguous permutation) + pvec fragment ----
__global__ void prep_build(const float* __restrict__ at_w,
                           const float* __restrict__ pvec) {
    int idx  = blockIdx.x * 256 + threadIdx.x;   // 0..1023
    int lane = idx & 31;
    int tig = lane & 3, gid = lane >> 2;
    {
        int tile = idx >> 5;
        int ks = tile >> 3, nt = tile & 7;
        int lk = 16 * tig + 4 * ks;
        int h  = nt * 8 + gid;
        uint2 v;
        v.x = pack_bf16x2(at_w[lk * NH + h],       at_w[(lk + 1) * NH + h]);
        v.y = pack_bf16x2(at_w[(lk + 2) * NH + h], at_w[(lk + 3) * NH + h]);
        g_wfrag[idx] = v;
    }
    if (idx < 128) {
        int ks = idx >> 5;
        int lk = 16 * tig + 4 * ks;
        uint2 v = make_uint2(0u, 0u);
        if (gid == 0) {   // column 0 of the extra tile
            v.x = pack_bf16x2(pvec[lk],     pvec[lk + 1]);
            v.y = pack_bf16x2(pvec[lk + 2], pvec[lk + 3]);
        }
        g_pfrag[idx] = v;
    }
}

__global__ __launch_bounds__(256, 2)
void afm_mma_kernel(const int*   __restrict__ x,      // [F, B]
                    const float* __restrict__ emb_v,  // [VOCAB, K]
                    const float* __restrict__ at_b,
                    const float* __restrict__ at_h,
                    const float* __restrict__ w0,
                    const float* __restrict__ w1,
                    float*       __restrict__ out)
{
    __shared__ uint32_t sVh[2][(NF + 1) * VSTRU];  // bf16x2 embeddings, 2 batches
    __shared__ float4   sBA4[32];
    __shared__ unsigned char sI[512], sJ[512];
    __shared__ float    sFm1[2], sRed[8];

    const int tid  = threadIdx.x;
    const int b0   = 2 * blockIdx.x;
    const int w    = tid >> 5;
    const int lane = tid & 31;
    const int gid  = lane >> 2;
    const int tig  = lane & 3;
    const int batch = w >> 2;
    const int wloc  = w & 3;

    // ---- W + pvec fragments in registers ----
    uint2 Wb[4][8];
    #pragma unroll
    for (int ks = 0; ks < 4; ks++)
        #pragma unroll
        for (int nt = 0; nt < 8; nt++)
            Wb[ks][nt] = __ldg(&g_wfrag[(ks * 8 + nt) * 32 + lane]);
    uint2 Ep[4];
    #pragma unroll
    for (int ks = 0; ks < 4; ks++)
        Ep[ks] = __ldg(&g_pfrag[ks * 32 + lane]);

    // ---- pair table (padded -> zero row) ----
    for (int p = tid; p < 512; p += 256) {
        if (p < PAIRS) {
            int pp = p, i = 0, off = 0;
            while (pp >= off + (NF - 1 - i)) { off += NF - 1 - i; i++; }
            sI[p] = (unsigned char)i;
            sJ[p] = (unsigned char)(i + 1 + pp - off);
        } else {
            sI[p] = ZROW; sJ[p] = ZROW;
        }
    }

    // ---- zero rows (both batches) ----
    if (tid < 2 * VSTRU) sVh[tid / VSTRU][ZROW * VSTRU + (tid % VSTRU)] = 0u;

    // ---- bias/at_h fragment table ----
    if (tid < 32) {
        int nt = tid >> 2, tg = tid & 3;
        int h0 = nt * 8 + 2 * tg;
        sBA4[tid] = make_float4(__ldg(&at_b[h0]),     __ldg(&at_h[h0]),
                                __ldg(&at_b[h0 + 1]), __ldg(&at_h[h0 + 1]));
    }

    // ---- gather embeddings for 2 batches, convert to bf16 ----
    for (int idx = tid; idx < 512; idx += 256) {
        int bt = idx >> 8, rem = idx & 255;
        int f = rem >> 3, q = rem & 7;
        int row = __ldg(&x[f * NB + b0 + bt]);
        const float4* src = (const float4*)emb_v + row * 16 + 2 * q;
        float4 v0 = __ldg(src), v1 = __ldg(src + 1);
        uint4 pk;
        pk.x = pack_bf16x2(v0.x, v0.y);
        pk.y = pack_bf16x2(v0.z, v0.w);
        pk.z = pack_bf16x2(v1.x, v1.y);
        pk.w = pack_bf16x2(v1.z, v1.w);
        *(uint4*)&sVh[bt][f * VSTRU + 4 * q] = pk;
    }

    // ---- first-order FM ----
    if (wloc == 0) {
        int row = __ldg(&x[lane * NB + b0 + batch]);
        float v = __ldg(&w1[row]);
        #pragma unroll
        for (int off = 16; off >= 1; off >>= 1)
            v += __shfl_xor_sync(0xffffffffu, v, off);
        if (lane == 0) sFm1[batch] = v + __ldg(w0);
    }
    __syncthreads();

    float acc = 0.f;   // Σ score_p * (VV[p].pvec)

    const uint32_t* vb = sVh[batch];
    const int ub = 8 * tig;

    #pragma unroll 2
    for (int t = 0; t < 8; t++) {
        const int p1 = t * 64 + wloc * 16 + gid;
        const uint32_t* ri1 = vb + sI[p1] * VSTRU + ub;
        const uint32_t* rj1 = vb + sJ[p1] * VSTRU + ub;
        const uint32_t* ri2 = vb + sI[p1 + 8] * VSTRU + ub;
        const uint32_t* rj2 = vb + sJ[p1 + 8] * VSTRU + ub;

        // ---- A fragments: 8 LDS.128 + 16 HMUL2 ----
        uint4 i0 = *(const uint4*)ri1, i1 = *(const uint4*)(ri1 + 4);
        uint4 j0 = *(const uint4*)rj1, j1 = *(const uint4*)(rj1 + 4);
        uint4 m0 = *(const uint4*)ri2, m1 = *(const uint4*)(ri2 + 4);
        uint4 n0 = *(const uint4*)rj2, n1 = *(const uint4*)(rj2 + 4);

        uint32_t af[4][4];
        af[0][0] = mul_bf16x2(i0.x, j0.x);  af[0][2] = mul_bf16x2(i0.y, j0.y);
        af[1][0] = mul_bf16x2(i0.z, j0.z);  af[1][2] = mul_bf16x2(i0.w, j0.w);
        af[2][0] = mul_bf16x2(i1.x, j1.x);  af[2][2] = mul_bf16x2(i1.y, j1.y);
        af[3][0] = mul_bf16x2(i1.z, j1.z);  af[3][2] = mul_bf16x2(i1.w, j1.w);
        af[0][1] = mul_bf16x2(m0.x, n0.x);  af[0][3] = mul_bf16x2(m0.y, n0.y);
        af[1][1] = mul_bf16x2(m0.z, n0.z);  af[1][3] = mul_bf16x2(m0.w, n0.w);
        af[2][1] = mul_bf16x2(m1.x, n1.x);  af[2][3] = mul_bf16x2(m1.y, n1.y);
        af[3][1] = mul_bf16x2(m1.z, n1.z);  af[3][3] = mul_bf16x2(m1.w, n1.w);

        // ---- extra tile: vp = VV . pvec (col 0; zero elsewhere) ----
        float e0 = 0.f, e1 = 0.f, e2 = 0.f, e3 = 0.f;
        #pragma unroll
        for (int ks = 0; ks < 4; ks++)
            mma_bf16(e0, e1, e2, e3,
                     af[ks][0], af[ks][1], af[ks][2], af[ks][3],
                     Ep[ks].x, Ep[ks].y);

        // ---- GEMM + fused score epilogue ----
        float s1 = 0.f, s2 = 0.f;
        #pragma unroll
        for (int nt = 0; nt < 8; nt++) {
            float d0 = 0.f, d1 = 0.f, d2 = 0.f, d3 = 0.f;
            #pragma unroll
            for (int ks = 0; ks < 4; ks++)
                mma_bf16(d0, d1, d2, d3,
                         af[ks][0], af[ks][1], af[ks][2], af[ks][3],
                         Wb[ks][nt].x, Wb[ks][nt].y);
            float4 ba = sBA4[nt * 4 + tig];
            s1 += fmaxf(d0 + ba.x, 0.f) * ba.y + fmaxf(d1 + ba.z, 0.f) * ba.w;
            s2 += fmaxf(d2 + ba.x, 0.f) * ba.y + fmaxf(d3 + ba.z, 0.f) * ba.w;
        }
        s1 += __shfl_xor_sync(0xffffffffu, s1, 1);
        s1 += __shfl_xor_sync(0xffffffffu, s1, 2);
        s2 += __shfl_xor_sync(0xffffffffu, s2, 1);
        s2 += __shfl_xor_sync(0xffffffffu, s2, 2);

        // contrib: valid on tig==0 lanes (e0/e2 are exact zeros elsewhere)
        acc = fmaf(s1, e0, acc);
        acc = fmaf(s2, e2, acc);
    }

    // ---- reduce acc across the warp (tig!=0 lanes carry zeros) ----
    #pragma unroll
    for (int off = 16; off >= 1; off >>= 1)
        acc += __shfl_xor_sync(0xffffffffu, acc, off);
    if (lane == 0) sRed[w] = acc;
    __syncthreads();

    if (tid < 2) {
        float at_fm = sRed[4 * tid] + sRed[4 * tid + 1] +
                      sRed[4 * tid + 2] + sRed[4 * tid + 3];
        float logit = at_fm + sFm1[tid];
        out[b0 + tid] = 1.f / (1.f + expf(-logit));
    }
}

extern "C" void kernel_launch(void* const* d_in, const int* in_sizes, int n_in,
                              void* d_out, int out_size) {
    const int*   x     = (const int*)  d_in[0];
    const float* emb_v = (const float*)d_in[1];
    const float* at_w  = (const float*)d_in[2];
    const float* at_b  = (const float*)d_in[3];
    const float* at_h  = (const float*)d_in[4];
    const float* pvec  = (const float*)d_in[5];
    const float* w0    = (const float*)d_in[6];
    const float* w1    = (const float*)d_in[7];
    float* out = (float*)d_out;

    prep_build<<<4, 256>>>(at_w, pvec);
    afm_mma_kernel<<<NB / 2, 256>>>(x, emb_v, at_b, at_h, w0, w1, out);
}